// round 3
// baseline (speedup 1.0000x reference)
#include <cuda_runtime.h>
#include <cstdint>

#define VOCAB  8000
#define HIDDEN 256
#define BATCH  32
#define SEQ    256
#define NROW   (SEQ * BATCH)   // 8192 output rows

// ---------------- scratch (device globals: allocation-free) ----------------
__device__ float g_WT[VOCAB * HIDDEN];   // W_ih transposed: [vocab][hidden]
__device__ float g_Xp[NROW * HIDDEN];    // gathered emb + b_ih + b_hh, rows = s*BATCH+b
__device__ float g_Y [NROW * HIDDEN];    // RNN hidden outputs

// ---------------- small PTX helpers ----------------
__device__ __forceinline__ uint32_t smem_u32(const void* p) {
    uint32_t a;
    asm("{ .reg .u64 t; cvta.to.shared.u64 t, %1; cvt.u32.u64 %0, t; }"
        : "=r"(a) : "l"(p));
    return a;
}
__device__ __forceinline__ uint32_t ctarank() {
    uint32_t r; asm("mov.u32 %0, %%cluster_ctarank;" : "=r"(r)); return r;
}
__device__ __forceinline__ void st_remote_f32(uint32_t laddr, uint32_t dst_rank, float v) {
    uint32_t ra;
    asm volatile("mapa.shared::cluster.u32 %0, %1, %2;" : "=r"(ra) : "r"(laddr), "r"(dst_rank));
    asm volatile("st.shared::cluster.f32 [%0], %1;" :: "r"(ra), "f"(v) : "memory");
}
__device__ __forceinline__ void cluster_sync_() {
    asm volatile("barrier.cluster.arrive.aligned;" ::: "memory");
    asm volatile("barrier.cluster.wait.aligned;"   ::: "memory");
}
__device__ __forceinline__ uint32_t f2tf32(float f) {
    uint32_t r; asm("cvt.rna.tf32.f32 %0, %1;" : "=r"(r) : "f"(f)); return r;
}

// ---------------- K0: transpose W_ih (HIDDEN x VOCAB) -> g_WT (VOCAB x HIDDEN) ----------------
__global__ void transpose_wih(const float* __restrict__ W) {
    __shared__ float tile[32][33];
    int vx = blockIdx.x * 32 + threadIdx.x;   // vocab index (read, coalesced)
    int ib = blockIdx.y * 32;                 // hidden base
    #pragma unroll
    for (int k = 0; k < 32; k += 8) {
        int i = ib + threadIdx.y + k;
        tile[threadIdx.y + k][threadIdx.x] = W[(size_t)i * VOCAB + vx];
    }
    __syncthreads();
    int i = ib + threadIdx.x;                 // hidden index (write, coalesced)
    #pragma unroll
    for (int k = 0; k < 32; k += 8) {
        int v = blockIdx.x * 32 + threadIdx.y + k;
        g_WT[(size_t)v * HIDDEN + i] = tile[threadIdx.x][threadIdx.y + k];
    }
}

// ---------------- K1: gather embedding + fold both biases ----------------
// Xp[s*BATCH+b][i] = W_ih[i][X[b][s]] + b_ih[i] + b_hh[i]
__global__ void gather_emb(const int* __restrict__ X,
                           const float* __restrict__ b_ih,
                           const float* __restrict__ b_hh) {
    int idx = blockIdx.x * blockDim.x + threadIdx.x;  // over NROW*64 float4s
    int r = idx >> 6;          // row = s*BATCH + b
    int q = idx & 63;          // float4 within hidden
    int s = r >> 5, b = r & 31;
    int v = X[b * SEQ + s];
    float4 e  = ((const float4*)g_WT)[(size_t)v * 64 + q];
    float4 bi = ((const float4*)b_ih)[q];
    float4 bh = ((const float4*)b_hh)[q];
    e.x += bi.x + bh.x;  e.y += bi.y + bh.y;
    e.z += bi.z + bh.z;  e.w += bi.w + bh.w;
    ((float4*)g_Xp)[(size_t)r * 64 + q] = e;
}

// ---------------- K2: RNN scan ----------------
// 16 clusters of 8 CTAs; cluster c handles batches {2c, 2c+1}.
// CTA rank owns hidden outputs [rank*32, rank*32+32) and keeps those 32 rows of
// W_hh (fp32, 32KB) in static SMEM for the whole scan. Per step: 8-way split-K
// dot, shfl reduce, tanh, push the 32-value slice to all 8 CTAs' next h buffer
// via DSMEM, one cluster barrier.
__global__ void __cluster_dims__(8, 1, 1) __launch_bounds__(256)
rnn_scan(const float* __restrict__ Whh, const float* __restrict__ h0) {
    __shared__ float Ws[32 * HIDDEN];        // 32KB: my 32 rows of W_hh
    __shared__ float hbuf[2][2][HIDDEN];     // [parity][batch][j]
    __shared__ float staging[2][32];         // freshly computed slice

    const int t = threadIdx.x;
    const uint32_t rank = ctarank();
    const int cid   = blockIdx.x >> 3;
    const int b0    = cid * 2;
    const int ibase = (int)rank * 32;

    // load my W rows (coalesced float4)
    {
        const float4* Wg = (const float4*)(Whh + (size_t)ibase * HIDDEN);
        float4* Ws4 = (float4*)Ws;
        #pragma unroll
        for (int k = 0; k < 8; k++) Ws4[k * 256 + t] = Wg[k * 256 + t];
    }
    // init h with h0 (local full copy, both batches)
    {
        int bb = t >> 7, j = (t & 127) * 2;
        float2 h2 = *(const float2*)&h0[(size_t)(b0 + bb) * HIDDEN + j];
        *(float2*)&hbuf[0][bb][j] = h2;
    }
    __syncthreads();
    cluster_sync_();

    const int o = t >> 3;        // my output within slice: 0..31
    const int p = t & 7;         // split-K part: 32 j's each
    const float4* W4 = (const float4*)(Ws + o * HIDDEN + p * 32);
    const int xcol = ibase + o;

    int par = 0;
    for (int s = 0; s < SEQ; s++) {
        const float4* ha = (const float4*)(&hbuf[par][0][p * 32]);
        const float4* hb = (const float4*)(&hbuf[par][1][p * 32]);
        float a0 = 0.f, a1 = 0.f;
        #pragma unroll
        for (int q = 0; q < 8; q++) {
            float4 w = W4[q], x = ha[q], y = hb[q];
            a0 += w.x * x.x; a1 += w.x * y.x;
            a0 += w.y * x.y; a1 += w.y * y.y;
            a0 += w.z * x.z; a1 += w.z * y.z;
            a0 += w.w * x.w; a1 += w.w * y.w;
        }
        #pragma unroll
        for (int m = 4; m; m >>= 1) {
            a0 += __shfl_xor_sync(0xffffffffu, a0, m);
            a1 += __shfl_xor_sync(0xffffffffu, a1, m);
        }
        if (p == 0) {
            size_t row = (size_t)(s * BATCH + b0) * HIDDEN + xcol;
            staging[0][o] = tanhf(a0 + g_Xp[row]);
            staging[1][o] = tanhf(a1 + g_Xp[row + HIDDEN]);
        }
        __syncthreads();

        const int np = par ^ 1;
        // write Y (coalesced 128B per batch-row slice)
        if (t < 64) {
            int bb = t >> 5, oo = t & 31;
            g_Y[(size_t)(s * BATCH + b0 + bb) * HIDDEN + ibase + oo] = staging[bb][oo];
        }
        // push my slice into every CTA's next-h buffer (incl. self) via DSMEM
        {
            int v = t & 63;  int bb = v >> 5, oo = v & 31;
            float val = staging[bb][oo];
            uint32_t laddr = smem_u32(&hbuf[np][bb][ibase + oo]);
            uint32_t d = (uint32_t)(t >> 6);   // 0..3
            st_remote_f32(laddr, d,     val);
            st_remote_f32(laddr, d + 4, val);
        }
        cluster_sync_();   // release DSMEM stores + separate read/write phases
        par = np;
    }
}

// ---------------- K3: output GEMM (tf32 mma.sync) ----------------
// out[r][v] = sum_k Y[r][k] * W_out[v][k] + b_out[v]
// BM=128, BN=64, BK=32; 8 warps in 4(M)x2(N); warp tile 32x32 via m16n8k8.
__device__ __forceinline__ void mma_tf32(float* d, const uint32_t* a, const uint32_t* b) {
    asm volatile(
        "mma.sync.aligned.m16n8k8.row.col.f32.tf32.tf32.f32 "
        "{%0,%1,%2,%3}, {%4,%5,%6,%7}, {%8,%9}, {%0,%1,%2,%3};"
        : "+f"(d[0]), "+f"(d[1]), "+f"(d[2]), "+f"(d[3])
        : "r"(a[0]), "r"(a[1]), "r"(a[2]), "r"(a[3]), "r"(b[0]), "r"(b[1]));
}

__global__ __launch_bounds__(256)
void gemm_out(const float* __restrict__ Wout, const float* __restrict__ bout,
              float* __restrict__ out) {
    __shared__ uint32_t As[128 * 36];   // stride 36 -> conflict-free frag reads
    __shared__ uint32_t Bs[64 * 36];

    const int t = threadIdx.x;
    const int warp = t >> 5, lane = t & 31;
    const int wm = warp & 3, wn = warp >> 2;
    const int r = lane >> 2, c = lane & 3;
    const int rowBase = blockIdx.y * 128;
    const int colBase = blockIdx.x * 64;

    float acc[2][4][4];
    #pragma unroll
    for (int mt = 0; mt < 2; mt++)
        #pragma unroll
        for (int nt = 0; nt < 4; nt++)
            #pragma unroll
            for (int i = 0; i < 4; i++) acc[mt][nt][i] = 0.f;

    for (int kt = 0; kt < 8; kt++) {
        // A tile: 128 x 32 from g_Y
        #pragma unroll
        for (int pp = 0; pp < 4; pp++) {
            int lin = pp * 256 + t;
            int m = lin >> 3, k4 = lin & 7;
            float4 f = *(const float4*)&g_Y[(size_t)(rowBase + m) * HIDDEN + kt * 32 + k4 * 4];
            uint4 u = make_uint4(f2tf32(f.x), f2tf32(f.y), f2tf32(f.z), f2tf32(f.w));
            *(uint4*)&As[m * 36 + k4 * 4] = u;
        }
        // B tile: 64 x 32 from W_out
        #pragma unroll
        for (int pp = 0; pp < 2; pp++) {
            int lin = pp * 256 + t;
            int n = lin >> 3, k4 = lin & 7;
            float4 f = *(const float4*)&Wout[(size_t)(colBase + n) * HIDDEN + kt * 32 + k4 * 4];
            uint4 u = make_uint4(f2tf32(f.x), f2tf32(f.y), f2tf32(f.z), f2tf32(f.w));
            *(uint4*)&Bs[n * 36 + k4 * 4] = u;
        }
        __syncthreads();

        #pragma unroll
        for (int ks = 0; ks < 4; ks++) {
            uint32_t a[2][4], bf[4][2];
            #pragma unroll
            for (int mt = 0; mt < 2; mt++) {
                int mb = wm * 32 + mt * 16;
                a[mt][0] = As[(mb + r    ) * 36 + ks * 8 + c    ];
                a[mt][1] = As[(mb + r + 8) * 36 + ks * 8 + c    ];
                a[mt][2] = As[(mb + r    ) * 36 + ks * 8 + c + 4];
                a[mt][3] = As[(mb + r + 8) * 36 + ks * 8 + c + 4];
            }
            #pragma unroll
            for (int nt = 0; nt < 4; nt++) {
                int nb = wn * 32 + nt * 8 + r;
                bf[nt][0] = Bs[nb * 36 + ks * 8 + c    ];
                bf[nt][1] = Bs[nb * 36 + ks * 8 + c + 4];
            }
            #pragma unroll
            for (int mt = 0; mt < 2; mt++)
                #pragma unroll
                for (int nt = 0; nt < 4; nt++)
                    mma_tf32(acc[mt][nt], a[mt], bf[nt]);
        }
        __syncthreads();
    }

    // epilogue: add bias, STG.64 pairs
    #pragma unroll
    for (int mt = 0; mt < 2; mt++) {
        int r0 = rowBase + wm * 32 + mt * 16 + r;
        #pragma unroll
        for (int nt = 0; nt < 4; nt++) {
            int col = colBase + wn * 32 + nt * 8 + c * 2;
            float bo0 = bout[col], bo1 = bout[col + 1];
            float2 v0 = make_float2(acc[mt][nt][0] + bo0, acc[mt][nt][1] + bo1);
            float2 v1 = make_float2(acc[mt][nt][2] + bo0, acc[mt][nt][3] + bo1);
            *(float2*)&out[(size_t)r0       * VOCAB + col] = v0;
            *(float2*)&out[(size_t)(r0 + 8) * VOCAB + col] = v1;
        }
    }
}

// ---------------- K4: h_last tail (last 32 rows of Y == h after step SEQ-1) ----------------
__global__ void tail_copy(float* __restrict__ out) {
    int t = blockIdx.x * blockDim.x + threadIdx.x;   // 0..8191
    out[(size_t)NROW * VOCAB + t] = g_Y[(size_t)(NROW - BATCH) * HIDDEN + t];
}

// ---------------- launch ----------------
extern "C" void kernel_launch(void* const* d_in, const int* in_sizes, int n_in,
                              void* d_out, int out_size) {
    const int*   X     = (const int*)  d_in[0];
    const float* h0    = (const float*)d_in[1];
    const float* W_ih  = (const float*)d_in[2];
    const float* b_ih  = (const float*)d_in[3];
    const float* W_hh  = (const float*)d_in[4];
    const float* b_hh  = (const float*)d_in[5];
    const float* W_out = (const float*)d_in[6];
    const float* b_out = (const float*)d_in[7];
    float* out = (float*)d_out;

    transpose_wih<<<dim3(VOCAB / 32, HIDDEN / 32), dim3(32, 8)>>>(W_ih);
    gather_emb<<<(NROW * 64) / 256, 256>>>(X, b_ih, b_hh);
    rnn_scan<<<128, 256>>>(W_hh, h0);
    gemm_out<<<dim3(VOCAB / 64, NROW / 128), 256>>>(W_out, b_out, out);
    if ((long long)out_size >= (long long)NROW * VOCAB + BATCH * HIDDEN)
        tail_copy<<<BATCH, HIDDEN>>>(out);
}

// round 4
// speedup vs baseline: 3.8620x; 3.8620x over previous
#include <cuda_runtime.h>
#include <cstdint>

#define VOCAB  8000
#define HIDDEN 256
#define BATCH  32
#define SEQ    256
#define NROW   (SEQ * BATCH)   // 8192 output rows

// ---------------- scratch (device globals: allocation-free) ----------------
__device__ float g_WT[VOCAB * HIDDEN];   // W_ih transposed: [vocab][hidden]
__device__ float g_Xp[NROW * HIDDEN];    // gathered emb + b_ih + b_hh, rows = s*BATCH+b
__device__ float g_Y [NROW * HIDDEN];    // RNN hidden outputs (tf32-rounded for GEMM)
__device__ float g_Wo[VOCAB * HIDDEN];   // W_out pre-rounded to tf32
__device__ float g_hlast[BATCH * HIDDEN];// exact fp32 final hidden state

extern __shared__ unsigned char dynsm[];

// ---------------- helpers ----------------
__device__ __forceinline__ uint32_t smem_u32(const void* p) {
    uint32_t a;
    asm("{ .reg .u64 t; cvta.to.shared.u64 t, %1; cvt.u32.u64 %0, t; }"
        : "=r"(a) : "l"(p));
    return a;
}
__device__ __forceinline__ uint32_t f2tf32(float f) {
    uint32_t r; asm("cvt.rna.tf32.f32 %0, %1;" : "=r"(r) : "f"(f)); return r;
}
__device__ __forceinline__ void fma2(uint64_t& d, uint64_t a, uint64_t b) {
    asm("fma.rn.f32x2 %0, %1, %2, %0;" : "+l"(d) : "l"(a), "l"(b));
}
__device__ __forceinline__ float lo32(uint64_t v) { return __uint_as_float((uint32_t)v); }
__device__ __forceinline__ float hi32(uint64_t v) { return __uint_as_float((uint32_t)(v >> 32)); }
__device__ __forceinline__ void cpa16(uint32_t dst, const void* src) {
    asm volatile("cp.async.cg.shared.global [%0], [%1], 16;" :: "r"(dst), "l"(src));
}

// ---------------- K0: transpose W_ih (HIDDEN x VOCAB) -> g_WT (VOCAB x HIDDEN) ----------------
__global__ void transpose_wih(const float* __restrict__ W) {
    __shared__ float tile[32][33];
    int vx = blockIdx.x * 32 + threadIdx.x;
    int ib = blockIdx.y * 32;
    #pragma unroll
    for (int k = 0; k < 32; k += 8) {
        int i = ib + threadIdx.y + k;
        tile[threadIdx.y + k][threadIdx.x] = W[(size_t)i * VOCAB + vx];
    }
    __syncthreads();
    int i = ib + threadIdx.x;
    #pragma unroll
    for (int k = 0; k < 32; k += 8) {
        int v = blockIdx.x * 32 + threadIdx.y + k;
        g_WT[(size_t)v * HIDDEN + i] = tile[threadIdx.x][threadIdx.y + k];
    }
}

// ---------------- K1: gather embedding + fold both biases ----------------
__global__ void gather_emb(const int* __restrict__ X,
                           const float* __restrict__ b_ih,
                           const float* __restrict__ b_hh) {
    int idx = blockIdx.x * blockDim.x + threadIdx.x;
    int r = idx >> 6, q = idx & 63;
    int s = r >> 5, b = r & 31;
    int v = X[b * SEQ + s];
    float4 e  = ((const float4*)g_WT)[(size_t)v * 64 + q];
    float4 bi = ((const float4*)b_ih)[q];
    float4 bh = ((const float4*)b_hh)[q];
    e.x += bi.x + bh.x;  e.y += bi.y + bh.y;
    e.z += bi.z + bh.z;  e.w += bi.w + bh.w;
    ((float4*)g_Xp)[(size_t)r * 64 + q] = e;
}

// ---------------- K1b: pre-round W_out to tf32 ----------------
__global__ void round_wout(const float* __restrict__ Wout) {
    int i = blockIdx.x * blockDim.x + threadIdx.x;  // over VOCAB*HIDDEN/4 float4s
    float4 f = ((const float4*)Wout)[i];
    uint4 u = make_uint4(f2tf32(f.x), f2tf32(f.y), f2tf32(f.z), f2tf32(f.w));
    ((uint4*)g_Wo)[i] = u;
}

// ---------------- K2: RNN scan (no clusters; one batch per CTA) ----------------
// 32 CTAs, 1024 threads. W_hh rows 0..127 in SMEM (stride 258, conflict-free
// LDS.64), rows 128..255 in registers (32 regs/thread). h (256 floats) in SMEM,
// broadcast-read. fp32-exact recurrence via packed fma.rn.f32x2.
#define WS_STRIDE 258
#define WS_FLOATS (128 * WS_STRIDE)               // 33024
#define H_OFF     WS_FLOATS                       // 256 floats
#define PART_OFF  (H_OFF + 256)                   // 16*132 = 2112 floats
#define XBUF_OFF  (PART_OFF + 2112)               // 256 floats
#define RNN_SMEM  ((XBUF_OFF + 256) * 4)          // 142592 bytes

__global__ void __launch_bounds__(1024, 1)
rnn_scan2(const float* __restrict__ Whh, const float* __restrict__ h0) {
    float* sm   = (float*)dynsm;
    float* Ws   = sm;                // [128][258]
    float* hbuf = sm + H_OFF;        // [256]
    float* part = sm + PART_OFF;     // [16][132]
    float* xbuf = sm + XBUF_OFF;     // [256]

    const int t = threadIdx.x;
    const int b = blockIdx.x;
    const int o = t & 127;           // output row within half
    const int p = t >> 7;            // K-part 0..7 (32 j's each)

    // load SMEM half of W (rows 0..127), padded stride
    for (int idx = t; idx < 128 * 256; idx += 1024) {
        int r = idx >> 8, c = idx & 255;
        Ws[r * WS_STRIDE + c] = Whh[r * 256 + c];
    }
    // register half of W: row 128+o, cols [p*32, p*32+32)
    uint64_t wr[16];
    {
        const uint64_t* wsrc = (const uint64_t*)(Whh + (size_t)(128 + o) * 256 + p * 32);
        #pragma unroll
        for (int i = 0; i < 16; i++) wr[i] = wsrc[i];
    }
    if (t < 256) hbuf[t] = h0[b * 256 + t];
    __syncthreads();

    const uint64_t* wss  = (const uint64_t*)(Ws + o * WS_STRIDE + p * 32); // even offset -> 8B aligned
    const uint64_t* hseg = (const uint64_t*)(hbuf) + p * 16;

    for (int s = 0; s < SEQ; s++) {
        // early prefetch of this step's Xp row (latency hidden under phase A)
        float4 xv;
        if (t < 64)
            xv = ((const float4*)(g_Xp + (size_t)(s * BATCH + b) * HIDDEN))[t];

        // phase A: partial dot products
        uint64_t accs = 0, accr = 0;
        #pragma unroll
        for (int j = 0; j < 16; j++) {
            uint64_t h2 = hseg[j];       // broadcast within warp
            fma2(accs, wss[j], h2);
            fma2(accr, wr[j],  h2);
        }
        part[p * 132 + o]       = lo32(accs) + hi32(accs);   // rows 0..127
        part[(8 + p) * 132 + o] = lo32(accr) + hi32(accr);   // rows 128..255
        if (t < 64) ((float4*)xbuf)[t] = xv;
        __syncthreads();

        // phase B: reduce 8 partials, add Xp, tanh, update h, emit Y
        if (t < 256) {
            int w = t >> 7, oo = t & 127;
            float sum = 0.f;
            #pragma unroll
            for (int q = 0; q < 8; q++) sum += part[(w * 8 + q) * 132 + oo];
            float v = tanhf(sum + xbuf[t]);
            hbuf[t] = v;
            g_Y[(size_t)(s * BATCH + b) * HIDDEN + t] = __uint_as_float(f2tf32(v));
            if (s == SEQ - 1) g_hlast[b * 256 + t] = v;
        }
        __syncthreads();
    }
}

// ---------------- K3: output GEMM (tf32 mma.sync, cp.async double-buffered) ----------------
// out[r][v] = sum_k Y[r][k] * W_out[v][k] + b_out[v]
// BM=128, BN=64, BK=32; 8 warps 4(M)x2(N); warp tile 32x32 via m16n8k8.
// Inputs pre-rounded to tf32 (g_Y, g_Wo) -> staging is a raw 16B async copy.
#define STG_FLOATS (128 * 36 + 64 * 36)   // 6912 per stage
#define GEMM_SMEM  (2 * STG_FLOATS * 4)   // 55296 bytes

__device__ __forceinline__ void mma_tf32(float* d, const uint32_t* a, const uint32_t* b) {
    asm volatile(
        "mma.sync.aligned.m16n8k8.row.col.f32.tf32.tf32.f32 "
        "{%0,%1,%2,%3}, {%4,%5,%6,%7}, {%8,%9}, {%0,%1,%2,%3};"
        : "+f"(d[0]), "+f"(d[1]), "+f"(d[2]), "+f"(d[3])
        : "r"(a[0]), "r"(a[1]), "r"(a[2]), "r"(a[3]), "r"(b[0]), "r"(b[1]));
}

__global__ __launch_bounds__(256)
void gemm_out(const float* __restrict__ bout, float* __restrict__ out) {
    uint32_t* smbase = (uint32_t*)dynsm;
    const int t = threadIdx.x;
    const int warp = t >> 5, lane = t & 31;
    const int wm = warp & 3, wn = warp >> 2;
    const int r = lane >> 2, c = lane & 3;
    const int rowBase = blockIdx.y * 128;
    const int colBase = blockIdx.x * 64;

    const uint32_t sm0 = smem_u32(smbase);

    float acc[2][4][4];
    #pragma unroll
    for (int mt = 0; mt < 2; mt++)
        #pragma unroll
        for (int nt = 0; nt < 4; nt++)
            #pragma unroll
            for (int i = 0; i < 4; i++) acc[mt][nt][i] = 0.f;

    // async-load one k-tile (kt) into stage st
    auto load_stage = [&](int kt, int st) {
        uint32_t abase = sm0 + st * (STG_FLOATS * 4);
        uint32_t bbase = abase + 128 * 36 * 4;
        #pragma unroll
        for (int q = 0; q < 4; q++) {          // A: 128x32
            int lin = q * 256 + t;
            int m = lin >> 3, k4 = lin & 7;
            cpa16(abase + (m * 36 + k4 * 4) * 4,
                  g_Y + (size_t)(rowBase + m) * HIDDEN + kt * 32 + k4 * 4);
        }
        #pragma unroll
        for (int q = 0; q < 2; q++) {          // B: 64x32
            int lin = q * 256 + t;
            int n = lin >> 3, k4 = lin & 7;
            cpa16(bbase + (n * 36 + k4 * 4) * 4,
                  g_Wo + (size_t)(colBase + n) * HIDDEN + kt * 32 + k4 * 4);
        }
        asm volatile("cp.async.commit_group;");
    };

    load_stage(0, 0);

    for (int kt = 0; kt < 8; kt++) {
        if (kt < 7) {
            load_stage(kt + 1, (kt + 1) & 1);
            asm volatile("cp.async.wait_group 1;");
        } else {
            asm volatile("cp.async.wait_group 0;");
        }
        __syncthreads();

        const uint32_t* As = smbase + (kt & 1) * STG_FLOATS;
        const uint32_t* Bs = As + 128 * 36;

        #pragma unroll
        for (int ks = 0; ks < 4; ks++) {
            uint32_t a[2][4], bf[4][2];
            #pragma unroll
            for (int mt = 0; mt < 2; mt++) {
                int mb = wm * 32 + mt * 16;
                a[mt][0] = As[(mb + r    ) * 36 + ks * 8 + c    ];
                a[mt][1] = As[(mb + r + 8) * 36 + ks * 8 + c    ];
                a[mt][2] = As[(mb + r    ) * 36 + ks * 8 + c + 4];
                a[mt][3] = As[(mb + r + 8) * 36 + ks * 8 + c + 4];
            }
            #pragma unroll
            for (int nt = 0; nt < 4; nt++) {
                int nb = wn * 32 + nt * 8 + r;
                bf[nt][0] = Bs[nb * 36 + ks * 8 + c    ];
                bf[nt][1] = Bs[nb * 36 + ks * 8 + c + 4];
            }
            #pragma unroll
            for (int mt = 0; mt < 2; mt++)
                #pragma unroll
                for (int nt = 0; nt < 4; nt++)
                    mma_tf32(acc[mt][nt], a[mt], bf[nt]);
        }
        __syncthreads();
    }

    // epilogue: add bias, STG.64 pairs
    #pragma unroll
    for (int mt = 0; mt < 2; mt++) {
        int r0 = rowBase + wm * 32 + mt * 16 + r;
        #pragma unroll
        for (int nt = 0; nt < 4; nt++) {
            int col = colBase + wn * 32 + nt * 8 + c * 2;
            float bo0 = bout[col], bo1 = bout[col + 1];
            float2 v0 = make_float2(acc[mt][nt][0] + bo0, acc[mt][nt][1] + bo1);
            float2 v1 = make_float2(acc[mt][nt][2] + bo0, acc[mt][nt][3] + bo1);
            *(float2*)&out[(size_t)r0       * VOCAB + col] = v0;
            *(float2*)&out[(size_t)(r0 + 8) * VOCAB + col] = v1;
        }
    }
}

// ---------------- K4: h_last tail (exact fp32) ----------------
__global__ void tail_copy(float* __restrict__ out) {
    int t = blockIdx.x * blockDim.x + threadIdx.x;   // 0..8191
    out[(size_t)NROW * VOCAB + t] = g_hlast[t];
}

// ---------------- launch ----------------
extern "C" void kernel_launch(void* const* d_in, const int* in_sizes, int n_in,
                              void* d_out, int out_size) {
    const int*   X     = (const int*)  d_in[0];
    const float* h0    = (const float*)d_in[1];
    const float* W_ih  = (const float*)d_in[2];
    const float* b_ih  = (const float*)d_in[3];
    const float* W_hh  = (const float*)d_in[4];
    const float* b_hh  = (const float*)d_in[5];
    const float* W_out = (const float*)d_in[6];
    const float* b_out = (const float*)d_in[7];
    float* out = (float*)d_out;

    cudaFuncSetAttribute(rnn_scan2, cudaFuncAttributeMaxDynamicSharedMemorySize, RNN_SMEM);
    cudaFuncSetAttribute(gemm_out,  cudaFuncAttributeMaxDynamicSharedMemorySize, GEMM_SMEM);

    transpose_wih<<<dim3(VOCAB / 32, HIDDEN / 32), dim3(32, 8)>>>(W_ih);
    gather_emb<<<(NROW * 64) / 256, 256>>>(X, b_ih, b_hh);
    round_wout<<<(VOCAB * HIDDEN / 4) / 256, 256>>>(W_out);
    rnn_scan2<<<BATCH, 1024, RNN_SMEM>>>(W_hh, h0);
    gemm_out<<<dim3(VOCAB / 64, NROW / 128), 256, GEMM_SMEM>>>(b_out, out);
    if ((long long)out_size >= (long long)NROW * VOCAB + BATCH * HIDDEN)
        tail_copy<<<BATCH, HIDDEN>>>(out);
}